// round 12
// baseline (speedup 1.0000x reference)
#include <cuda_runtime.h>
#include <cuda_fp16.h>
#include <cstdint>

// GhostLinearTandem FUSED v2: one GEMM kernel with inline two-level-LUT dequant.
//  prepass: x fp32->fp16 (g_xh), lut fp32->fp16 (g_lut_h).
//  main: BM=512 (ALL of M) x BN=64 per CTA, grid 128 = single wave; idx read once.
//  v2: SINGLE barrier per stage. Pipeline per iter s:
//    STS B[s&1] (from regs) -> CP_WAIT0 -> barrier -> cp.async A(s+1)
//    -> LDG idx(s+2) -> LUT-gather idx(s+1) (latency hidden under MMA) -> MMA(s).
//  Safety: barrier(s) is after MMA(s-1) in all warps, so overwriting
//  A[(s+1)&1] (last read by MMA(s-1)) and B[s&1] (last read by MMA(s-2)) is safe.

#define M_TOTAL 512
#define N_TOTAL 8192
#define K_TOTAL 4096

__device__ __align__(16) __half g_xh[(size_t)M_TOTAL * K_TOTAL];  // 4 MiB
__device__ __align__(16) __half g_lut_h[65536];                   // 128 KiB

__device__ __forceinline__ uint32_t smem_u32(const void* p) {
    uint32_t a;
    asm("{ .reg .u64 t; cvta.to.shared.u64 t, %1; cvt.u32.u64 %0, t; }"
        : "=r"(a) : "l"(p));
    return a;
}
__device__ __forceinline__ uint32_t h2_to_u32(__half2 h) {
    uint32_t u; *(__half2*)&u = h; return u;
}
#define SWZ128(off) ((off) ^ (((off) >> 3) & 0x70))
// pair-packed rows: two 64B logical rows per 128B swizzle atom
#define PB(r, cb) ((((r) >> 1) * 128) + (((r) & 1) * 64) + (cb))

#define CP16(dst, src) \
    asm volatile("cp.async.cg.shared.global [%0], [%1], 16;" :: "r"(dst), "l"(src))
#define CP_COMMIT() asm volatile("cp.async.commit_group;")
#define CP_WAIT0()  asm volatile("cp.async.wait_group 0;")

#define LDSM_X4(r0, r1, r2, r3, addr)                                     \
    asm volatile("ldmatrix.sync.aligned.m8n8.x4.shared.b16 {%0,%1,%2,%3}, [%4];" \
                 : "=r"(r0), "=r"(r1), "=r"(r2), "=r"(r3) : "r"(addr))

#define MMA_F16(d, a0, a1, a2, a3, b0, b1)                             \
    asm volatile(                                                      \
        "mma.sync.aligned.m16n8k16.row.col.f32.f16.f16.f32 "           \
        "{%0,%1,%2,%3}, {%4,%5,%6,%7}, {%8,%9}, {%0,%1,%2,%3};\n"      \
        : "+f"((d)[0]), "+f"((d)[1]), "+f"((d)[2]), "+f"((d)[3])       \
        : "r"(a0), "r"(a1), "r"(a2), "r"(a3), "r"(b0), "r"(b1))

// ---------------------------------------------------------------- prepass
__global__ __launch_bounds__(256)
void ghost_prepass(const float* __restrict__ x, const float* __restrict__ lut) {
    int t = blockIdx.x * blockDim.x + threadIdx.x;
    int stride = gridDim.x * blockDim.x;
    const float4* xp = (const float4*)x;
    for (int g = t; g < M_TOTAL * K_TOTAL / 8; g += stride) {
        float4 u = xp[2 * g], v = xp[2 * g + 1];
        __half2 h[4] = {__floats2half2_rn(u.x, u.y), __floats2half2_rn(u.z, u.w),
                        __floats2half2_rn(v.x, v.y), __floats2half2_rn(v.z, v.w)};
        *(uint4*)&g_xh[(size_t)g * 8] = *(uint4*)h;
    }
    const float4* lp = (const float4*)lut;
    for (int g = t; g < 65536 / 8; g += stride) {
        float4 u = lp[2 * g], v = lp[2 * g + 1];
        __half2 h[4] = {__floats2half2_rn(u.x, u.y), __floats2half2_rn(u.z, u.w),
                        __floats2half2_rn(v.x, v.y), __floats2half2_rn(v.z, v.w)};
        *(uint4*)&g_lut_h[g * 8] = *(uint4*)h;
    }
}

// ---------------------------------------------------------------- fused GEMM
#define BM 512
#define BN 64
#define BKH 32                        // halves per stage (64 B per logical row)
#define NS (K_TOTAL / BKH)            // 128 stages
#define LUT_BYTES 131072
#define A_ST (BM * 64)                // 32768 B per A buffer
#define B_ST (BN * 64)                // 4096 B per B buffer
#define AOFF LUT_BYTES
#define BOFF (LUT_BYTES + 2 * A_ST)
#define SMEM_FUSED (LUT_BYTES + 2 * A_ST + 2 * B_ST)  // 204800
#define THREADS 512

__global__ __launch_bounds__(THREADS, 1)
void ghost_fused(const int* __restrict__ base_idx,
                 const int* __restrict__ fine_idx,
                 const float* __restrict__ scale,
                 float* __restrict__ out) {
    extern __shared__ char smem[];
    const uint32_t sb = smem_u32(smem);
    __half* lut_s = (__half*)smem;
    const int tid = threadIdx.x;
    const int warp = tid >> 5, lane = tid & 31;
    const int n0 = blockIdx.x * BN;

    // ---- LUT -> smem ----
    {
        const uint4* src = (const uint4*)g_lut_h;  // 8192 uint4
        uint4* dst = (uint4*)smem;
        #pragma unroll
        for (int i = 0; i < 16; i++) dst[tid + i * THREADS] = src[tid + i * THREADS];
    }

    // ---- dequant role: thread t -> B row (t>>3), 4 elems at (t&7)*4 ----
    const int drow = tid >> 3;
    const int dk4 = (tid & 7) * 4;
    const float scl = scale[n0 + drow];
    const int* bsrc = base_idx + (size_t)(n0 + drow) * K_TOTAL + dk4;
    const int* fsrc = fine_idx + (size_t)(n0 + drow) * K_TOTAL + dk4;
    const uint32_t bsw = SWZ128(PB(drow, dk4 * 2));   // STS byte offset (swizzled)

    // ---- A loader role: 4 x 16B chunks per thread per stage ----
    auto load_A = [&](int s, int slot) {
        const int kh = s * BKH;
        #pragma unroll
        for (int i = 0; i < 4; i++) {
            int c = tid + i * THREADS;
            int row = c >> 2, ci = c & 3;
            CP16(sb + AOFF + slot * A_ST + SWZ128(PB(row, ci * 16)),
                 g_xh + (size_t)row * K_TOTAL + kh + ci * 8);
        }
        CP_COMMIT();
    };

    // ---- warp tiling: 8 warps along M (64 rows), 2 along N (32 cols) ----
    const int warp_m = warp >> 1;
    const int warp_n = warp & 1;
    const int a_row0 = warp_m * 64 + ((lane >> 3) & 1) * 8 + (lane & 7);
    const int a_koff = (lane >> 4) * 8;
    const int b_row0 = warp_n * 32 + ((lane >> 4) & 1) * 8 + (lane & 7);
    const int b_koff = ((lane >> 3) & 1) * 8;

    float acc[4][4][4];
    #pragma unroll
    for (int mt = 0; mt < 4; mt++)
        #pragma unroll
        for (int nt = 0; nt < 4; nt++)
            #pragma unroll
            for (int r = 0; r < 4; r++) acc[mt][nt][r] = 0.0f;

    // ---- prologue ----
    // idx ring: I[k&1] holds idx(k). Load idx(0), idx(1).
    int4 Ib[2], If[2];
    Ib[0] = *(const int4*)bsrc;            If[0] = *(const int4*)fsrc;
    Ib[1] = *(const int4*)(bsrc + BKH);    If[1] = *(const int4*)(fsrc + BKH);
    load_A(0, 0);
    __syncthreads();   // LUT resident before first gather

    // gather stage 0 -> Breg
    uint2 Breg;
    {
        int4 b = Ib[0], f = If[0];
        __half2 lo = __floats2half2_rn(__half2float(lut_s[(b.x << 8) + f.x]) * scl,
                                       __half2float(lut_s[(b.y << 8) + f.y]) * scl);
        __half2 hi = __floats2half2_rn(__half2float(lut_s[(b.z << 8) + f.z]) * scl,
                                       __half2float(lut_s[(b.w << 8) + f.w]) * scl);
        Breg = make_uint2(h2_to_u32(lo), h2_to_u32(hi));
    }

    for (int s = 0; s < NS; ++s) {
        const int buf = s & 1;

        // (1) publish B(s) from regs
        *(uint2*)(smem + BOFF + buf * B_ST + bsw) = Breg;

        // (2) A(s) landed
        CP_WAIT0();
        // (3) one barrier: B(s)+A(s) visible; all warps past MMA(s-1)
        __syncthreads();

        // (4) next A tile (slot buf^1 free: its readers MMA(s-1) are done)
        if (s + 1 < NS) load_A(s + 1, buf ^ 1);

        // (5) idx(s+2) prefetch into ring (slot (s+2)&1 == buf, already consumed)
        if (s + 2 < NS) {
            Ib[buf] = *(const int4*)(bsrc + (s + 2) * BKH);
            If[buf] = *(const int4*)(fsrc + (s + 2) * BKH);
        }

        // (6) gather idx(s+1) -> Breg; LDS latency hides under MMA below
        if (s + 1 < NS) {
            int4 b = Ib[(s + 1) & 1], f = If[(s + 1) & 1];
            __half2 lo = __floats2half2_rn(
                __half2float(lut_s[(b.x << 8) + f.x]) * scl,
                __half2float(lut_s[(b.y << 8) + f.y]) * scl);
            __half2 hi = __floats2half2_rn(
                __half2float(lut_s[(b.z << 8) + f.z]) * scl,
                __half2float(lut_s[(b.w << 8) + f.w]) * scl);
            Breg = make_uint2(h2_to_u32(lo), h2_to_u32(hi));
        }

        // (7) MMA on buf
        const uint32_t Abase = sb + AOFF + buf * A_ST;
        const uint32_t Bbase = sb + BOFF + buf * B_ST;
        #pragma unroll
        for (int ks = 0; ks < 2; ks++) {
            const int kb = ks * 32;
            uint32_t af[4][4], bf[2][4];
            #pragma unroll
            for (int mt = 0; mt < 4; mt++) {
                uint32_t ad = Abase + SWZ128(PB(a_row0 + mt * 16, a_koff * 2 + kb));
                LDSM_X4(af[mt][0], af[mt][1], af[mt][2], af[mt][3], ad);
            }
            #pragma unroll
            for (int np = 0; np < 2; np++) {
                uint32_t bd = Bbase + SWZ128(PB(b_row0 + np * 16, b_koff * 2 + kb));
                LDSM_X4(bf[np][0], bf[np][1], bf[np][2], bf[np][3], bd);
            }
            #pragma unroll
            for (int mt = 0; mt < 4; mt++)
                #pragma unroll
                for (int nt = 0; nt < 4; nt++)
                    MMA_F16(acc[mt][nt],
                            af[mt][0], af[mt][1], af[mt][2], af[mt][3],
                            bf[nt >> 1][(nt & 1) * 2],
                            bf[nt >> 1][(nt & 1) * 2 + 1]);
        }
    }

    // ---- epilogue ----
    const int qid = lane >> 2, tg = lane & 3;
    #pragma unroll
    for (int mt = 0; mt < 4; mt++) {
        #pragma unroll
        for (int nt = 0; nt < 4; nt++) {
            int row = warp_m * 64 + mt * 16 + qid;
            int col = n0 + warp_n * 32 + nt * 8 + tg * 2;
            *(float2*)&out[(size_t)row * N_TOTAL + col] =
                make_float2(acc[mt][nt][0], acc[mt][nt][1]);
            *(float2*)&out[(size_t)(row + 8) * N_TOTAL + col] =
                make_float2(acc[mt][nt][2], acc[mt][nt][3]);
        }
    }
}

extern "C" void kernel_launch(void* const* d_in, const int* in_sizes, int n_in,
                              void* d_out, int out_size) {
    const float* x        = (const float*)d_in[0];
    const int*   base_idx = (const int*)d_in[1];
    const int*   fine_idx = (const int*)d_in[2];
    const float* scale    = (const float*)d_in[3];
    const float* lut      = (const float*)d_in[4];
    float* out = (float*)d_out;

    cudaFuncSetAttribute(ghost_fused, cudaFuncAttributeMaxDynamicSharedMemorySize,
                         SMEM_FUSED);

    ghost_prepass<<<296, 256>>>(x, lut);
    ghost_fused<<<N_TOTAL / BN, THREADS, SMEM_FUSED>>>(base_idx, fine_idx,
                                                       scale, out);
}

// round 13
// speedup vs baseline: 1.3698x; 1.3698x over previous
#include <cuda_runtime.h>
#include <cuda_fp16.h>
#include <cstdint>

// GhostLinearTandem, two-pass (best-known structure, R6 gemm verbatim):
//  pass 1 (ghost_dequant): W fp16 -> 64MiB scratch (LUT fp16 in smem), x -> fp16.
//    512 threads/CTA (128-reg budget) + explicit 4-group batching -> real MLP.
//  pass 2 (ghost_gemm): fp16 mma.sync m16n8k16, BM=BN=128, BK=64,
//    4 warps x (64x64), ldmatrix.x4 on SW128 smem, cp.async 3-stage ring,
//    2 CTAs/SM, grid (4,64) M-fastest (W L2 reuse).

#define M_TOTAL 512
#define N_TOTAL 8192
#define K_TOTAL 4096

__device__ __align__(16) __half g_W[(size_t)N_TOTAL * K_TOTAL];   // 64 MiB
__device__ __align__(16) __half g_xh[(size_t)M_TOTAL * K_TOTAL];  // 4 MiB

__device__ __forceinline__ uint32_t smem_u32(const void* p) {
    uint32_t a;
    asm("{ .reg .u64 t; cvta.to.shared.u64 t, %1; cvt.u32.u64 %0, t; }"
        : "=r"(a) : "l"(p));
    return a;
}
#define SWZ128(off) ((off) ^ (((off) >> 3) & 0x70))

#define CP16(dst, src) \
    asm volatile("cp.async.cg.shared.global [%0], [%1], 16;" :: "r"(dst), "l"(src))
#define CP_COMMIT() asm volatile("cp.async.commit_group;")
#define CP_WAIT1()  asm volatile("cp.async.wait_group 1;")

#define LDSM_X4(r0, r1, r2, r3, addr)                                     \
    asm volatile("ldmatrix.sync.aligned.m8n8.x4.shared.b16 {%0,%1,%2,%3}, [%4];" \
                 : "=r"(r0), "=r"(r1), "=r"(r2), "=r"(r3) : "r"(addr))

#define MMA_F16(d, a0, a1, a2, a3, b0, b1)                             \
    asm volatile(                                                      \
        "mma.sync.aligned.m16n8k16.row.col.f32.f16.f16.f32 "           \
        "{%0,%1,%2,%3}, {%4,%5,%6,%7}, {%8,%9}, {%0,%1,%2,%3};\n"      \
        : "+f"((d)[0]), "+f"((d)[1]), "+f"((d)[2]), "+f"((d)[3])       \
        : "r"(a0), "r"(a1), "r"(a2), "r"(a3), "r"(b0), "r"(b1))

// ---------------------------------------------------------------- pass 1
#define DQT 512   // threads (128-reg budget so 4-group batch fits in regs)

__global__ __launch_bounds__(DQT)
void ghost_dequant(const int* __restrict__ base_idx,
                   const int* __restrict__ fine_idx,
                   const float* __restrict__ scale,
                   const float* __restrict__ lut,
                   const float* __restrict__ x) {
    extern __shared__ __half lut_s[];  // 65536 fp16 = 128KB
    {
        const float4* lp = (const float4*)lut;       // 16384 float4
        #pragma unroll
        for (int i = threadIdx.x; i < 16384; i += DQT) {
            float4 u = lp[i];
            __half2 h[2] = {__floats2half2_rn(u.x, u.y),
                            __floats2half2_rn(u.z, u.w)};
            *(uint2*)&lut_s[i * 4] = *(uint2*)h;
        }
    }
    __syncthreads();

    size_t t = (size_t)blockIdx.x * blockDim.x + threadIdx.x;
    size_t stride = (size_t)gridDim.x * blockDim.x;

    // x fp32 -> fp16
    const float4* xp = (const float4*)x;
    for (size_t g = t; g < (size_t)M_TOTAL * K_TOTAL / 8; g += stride) {
        float4 u = xp[2 * g], v = xp[2 * g + 1];
        __half2 h[4] = {__floats2half2_rn(u.x, u.y), __floats2half2_rn(u.z, u.w),
                        __floats2half2_rn(v.x, v.y), __floats2half2_rn(v.z, v.w)};
        *(uint4*)&g_xh[g * 8] = *(uint4*)h;
    }

    // W dequant: 4-group batch (32 elems/iter/thread). Groups within a batch
    // are CONSECUTIVE for this thread (g*4+j) so each batch stays in-row
    // (512 groups per 4096-elem row; base t*4 is 4-aligned, row uniform per batch? 
    // g4 = (t + i*stride)*4 .. +3: same row iff (g4 % 512) <= 508 -> holds since
    // 4 | g4 and row-crossings happen at 512 boundaries; 4-group spans [g4,g4+3]
    // crosses only if g4 % 512 == 508,509,.. impossible except g4%512==508 -> 
    // handled by per-group row computation below (cheap).
    const int4* bp = (const int4*)base_idx;
    const int4* fp = (const int4*)fine_idx;
    const size_t NB = (size_t)N_TOTAL * K_TOTAL / 32;   // 4-group batches
    for (size_t gb = t; gb < NB; gb += stride) {
        size_t g0 = gb * 4;
        int4 b[8], f[8];
        #pragma unroll
        for (int j = 0; j < 8; j++) { b[j] = bp[2 * g0 + j]; f[j] = fp[2 * g0 + j]; }
        #pragma unroll
        for (int j = 0; j < 4; j++) {
            int row = (int)((g0 + j) >> 9);
            float scl = __ldg(&scale[row]);
            int4 b0 = b[2 * j], b1 = b[2 * j + 1];
            int4 f0 = f[2 * j], f1 = f[2 * j + 1];
            __half2 h[4];
            h[0] = __floats2half2_rn(__half2float(lut_s[(b0.x << 8) + f0.x]) * scl,
                                     __half2float(lut_s[(b0.y << 8) + f0.y]) * scl);
            h[1] = __floats2half2_rn(__half2float(lut_s[(b0.z << 8) + f0.z]) * scl,
                                     __half2float(lut_s[(b0.w << 8) + f0.w]) * scl);
            h[2] = __floats2half2_rn(__half2float(lut_s[(b1.x << 8) + f1.x]) * scl,
                                     __half2float(lut_s[(b1.y << 8) + f1.y]) * scl);
            h[3] = __floats2half2_rn(__half2float(lut_s[(b1.z << 8) + f1.z]) * scl,
                                     __half2float(lut_s[(b1.w << 8) + f1.w]) * scl);
            *(uint4*)&g_W[(g0 + j) * 8] = *(uint4*)h;
        }
    }
}

// ---------------------------------------------------------------- pass 2 (R6)
#define BM 128
#define BN 128
#define BKH 64                      // halves per stage (128 B per row)
#define NS (K_TOTAL / BKH)          // 64 stages
#define NSLOT 3
#define A_BYTES (BM * 128)          // 16384
#define STAGE_BYTES (2 * A_BYTES)   // A + B = 32768
#define SMEM_GEMM (NSLOT * STAGE_BYTES)  // 98304
#define THREADS 128                 // 4 warps, each 64x64

__global__ __launch_bounds__(THREADS, 2)
void ghost_gemm(float* __restrict__ out) {
    extern __shared__ char smem[];
    const uint32_t sb = smem_u32(smem);
    const int tid = threadIdx.x;
    const int warp = tid >> 5, lane = tid & 31;
    const int m0 = blockIdx.x * BM;   // M fastest -> W L2 reuse
    const int n0 = blockIdx.y * BN;

    const __half* Ag = g_xh + (size_t)m0 * K_TOTAL;
    const __half* Bg = g_W + (size_t)n0 * K_TOTAL;

    auto load_stage = [&](int s, int slot) {
        const int kh = s * BKH;
        #pragma unroll
        for (int i = 0; i < 16; i++) {
            int c = tid + i * THREADS;           // 0..2047
            int cc = c & 1023;
            int row = cc >> 3, ci = cc & 7;
            uint32_t dst = sb + slot * STAGE_BYTES + ((c < 1024) ? 0 : A_BYTES) +
                           SWZ128(row * 128 + ci * 16);
            const __half* src = (c < 1024)
                ? Ag + (size_t)row * K_TOTAL + kh + ci * 8
                : Bg + (size_t)row * K_TOTAL + kh + ci * 8;
            CP16(dst, src);
        }
        CP_COMMIT();
    };

    // warp tiling: 2 warps along M x 2 along N, each 64x64
    const int warp_m = warp & 1;
    const int warp_n = warp >> 1;

    const int a_row0 = warp_m * 64 + ((lane >> 3) & 1) * 8 + (lane & 7);
    const int a_koff = (lane >> 4) * 8;
    const int b_row0 = warp_n * 64 + ((lane >> 4) & 1) * 8 + (lane & 7);
    const int b_koff = ((lane >> 3) & 1) * 8;

    float acc[4][8][4];
    #pragma unroll
    for (int mt = 0; mt < 4; mt++)
        #pragma unroll
        for (int nt = 0; nt < 8; nt++)
            #pragma unroll
            for (int r = 0; r < 4; r++) acc[mt][nt][r] = 0.0f;

    load_stage(0, 0);
    load_stage(1, 1);

    int slot = 0;
    for (int s = 0; s < NS; ++s) {
        CP_WAIT1();
        __syncthreads();   // stage s resident in all threads' view

        const uint32_t Abase = sb + slot * STAGE_BYTES;
        const uint32_t Bbase = Abase + A_BYTES;

        #pragma unroll
        for (int ks = 0; ks < 4; ks++) {
            const int k0 = ks * 16;  // halves
            uint32_t af[4][4], bf[4][4];
            #pragma unroll
            for (int mt = 0; mt < 4; mt++) {
                uint32_t ad = Abase +
                    SWZ128((a_row0 + mt * 16) * 128 + (k0 + a_koff) * 2);
                LDSM_X4(af[mt][0], af[mt][1], af[mt][2], af[mt][3], ad);
            }
            #pragma unroll
            for (int np = 0; np < 4; np++) {
                uint32_t bd = Bbase +
                    SWZ128((b_row0 + np * 16) * 128 + (k0 + b_koff) * 2);
                LDSM_X4(bf[np][0], bf[np][1], bf[np][2], bf[np][3], bd);
            }
            #pragma unroll
            for (int mt = 0; mt < 4; mt++)
                #pragma unroll
                for (int nt = 0; nt < 8; nt++)
                    MMA_F16(acc[mt][nt],
                            af[mt][0], af[mt][1], af[mt][2], af[mt][3],
                            bf[nt >> 1][(nt & 1) * 2],
                            bf[nt >> 1][(nt & 1) * 2 + 1]);
        }

        if (s + 2 < NS)
            load_stage(s + 2, (slot + 2) % NSLOT);
        else
            CP_COMMIT();   // empty group keeps wait_group accounting exact
        slot = (slot + 1) % NSLOT;
    }

    // epilogue
    const int qid = lane >> 2, tg = lane & 3;
    #pragma unroll
    for (int mt = 0; mt < 4; mt++) {
        #pragma unroll
        for (int nt = 0; nt < 8; nt++) {
            int row = m0 + warp_m * 64 + mt * 16 + qid;
            int col = n0 + warp_n * 64 + nt * 8 + tg * 2;
            *(float2*)&out[(size_t)row * N_TOTAL + col] =
                make_float2(acc[mt][nt][0], acc[mt][nt][1]);
            *(float2*)&out[(size_t)(row + 8) * N_TOTAL + col] =
                make_float2(acc[mt][nt][2], acc[mt][nt][3]);
        }
    }
}

extern "C" void kernel_launch(void* const* d_in, const int* in_sizes, int n_in,
                              void* d_out, int out_size) {
    const float* x        = (const float*)d_in[0];
    const int*   base_idx = (const int*)d_in[1];
    const int*   fine_idx = (const int*)d_in[2];
    const float* scale    = (const float*)d_in[3];
    const float* lut      = (const float*)d_in[4];
    float* out = (float*)d_out;

    cudaFuncSetAttribute(ghost_dequant, cudaFuncAttributeMaxDynamicSharedMemorySize,
                         131072);
    cudaFuncSetAttribute(ghost_gemm, cudaFuncAttributeMaxDynamicSharedMemorySize,
                         SMEM_GEMM);

    ghost_dequant<<<148, DQT, 131072>>>(base_idx, fine_idx, scale, lut, x);
    dim3 grid(M_TOTAL / BM, N_TOTAL / BN);  // (4, 64), M fastest
    ghost_gemm<<<grid, THREADS, SMEM_GEMM>>>(out);
}

// round 14
// speedup vs baseline: 1.6419x; 1.1986x over previous
#include <cuda_runtime.h>
#include <cuda_fp16.h>
#include <cstdint>

// GhostLinearTandem, two-pass (best-known config, restored):
//  pass 1 (ghost_dequant): R8 form — 1024 thr/CTA (32 warps, latency-bound),
//    LUT fp16 in smem, simple 2x-unrolled group loop. ~62 µs measured.
//  pass 2 (ghost_gemm): R6 form — fp16 mma.sync m16n8k16, BM=BN=128, BK=64,
//    4 warps x (64x64), ldmatrix.x4 on SW128 smem, cp.async 3-stage ring,
//    2 CTAs/SM, grid (4,64). Tweak: stage-(s+2) cp.async issued right after
//    the barrier (before LDSM/MMA) -> ~2 stages of load flight time.

#define M_TOTAL 512
#define N_TOTAL 8192
#define K_TOTAL 4096

__device__ __align__(16) __half g_W[(size_t)N_TOTAL * K_TOTAL];   // 64 MiB
__device__ __align__(16) __half g_xh[(size_t)M_TOTAL * K_TOTAL];  // 4 MiB

__device__ __forceinline__ uint32_t smem_u32(const void* p) {
    uint32_t a;
    asm("{ .reg .u64 t; cvta.to.shared.u64 t, %1; cvt.u32.u64 %0, t; }"
        : "=r"(a) : "l"(p));
    return a;
}
#define SWZ128(off) ((off) ^ (((off) >> 3) & 0x70))

#define CP16(dst, src) \
    asm volatile("cp.async.cg.shared.global [%0], [%1], 16;" :: "r"(dst), "l"(src))
#define CP_COMMIT() asm volatile("cp.async.commit_group;")
#define CP_WAIT1()  asm volatile("cp.async.wait_group 1;")

#define LDSM_X4(r0, r1, r2, r3, addr)                                     \
    asm volatile("ldmatrix.sync.aligned.m8n8.x4.shared.b16 {%0,%1,%2,%3}, [%4];" \
                 : "=r"(r0), "=r"(r1), "=r"(r2), "=r"(r3) : "r"(addr))

#define MMA_F16(d, a0, a1, a2, a3, b0, b1)                             \
    asm volatile(                                                      \
        "mma.sync.aligned.m16n8k16.row.col.f32.f16.f16.f32 "           \
        "{%0,%1,%2,%3}, {%4,%5,%6,%7}, {%8,%9}, {%0,%1,%2,%3};\n"      \
        : "+f"((d)[0]), "+f"((d)[1]), "+f"((d)[2]), "+f"((d)[3])       \
        : "r"(a0), "r"(a1), "r"(a2), "r"(a3), "r"(b0), "r"(b1))

// ---------------------------------------------------------------- pass 1 (R8)
__global__ __launch_bounds__(1024)
void ghost_dequant(const int* __restrict__ base_idx,
                   const int* __restrict__ fine_idx,
                   const float* __restrict__ scale,
                   const float* __restrict__ lut,
                   const float* __restrict__ x) {
    extern __shared__ __half lut_s[];  // 65536 fp16 = 128KB
    #pragma unroll 4
    for (int i = threadIdx.x; i < 65536; i += 1024)
        lut_s[i] = __float2half_rn(lut[i]);
    __syncthreads();

    size_t t = (size_t)blockIdx.x * blockDim.x + threadIdx.x;
    size_t stride = (size_t)gridDim.x * blockDim.x;

    // x fp32 -> fp16
    const float4* xp = (const float4*)x;
    for (size_t g = t; g < (size_t)M_TOTAL * K_TOTAL / 8; g += stride) {
        float4 u = xp[2 * g], v = xp[2 * g + 1];
        __half2 h[4] = {__floats2half2_rn(u.x, u.y), __floats2half2_rn(u.z, u.w),
                        __floats2half2_rn(v.x, v.y), __floats2half2_rn(v.z, v.w)};
        *(uint4*)&g_xh[g * 8] = *(uint4*)h;
    }

    const int4* bp = (const int4*)base_idx;
    const int4* fp = (const int4*)fine_idx;
    const size_t NG = (size_t)N_TOTAL * K_TOTAL / 8;
    #pragma unroll 2
    for (size_t g = t; g < NG; g += stride) {
        int row = (int)(g >> 9);
        float scl = __ldg(&scale[row]);
        int4 b0 = bp[2 * g], b1 = bp[2 * g + 1];
        int4 f0 = fp[2 * g], f1 = fp[2 * g + 1];
        __half2 h[4];
        h[0] = __floats2half2_rn(__half2float(lut_s[(b0.x << 8) + f0.x]) * scl,
                                 __half2float(lut_s[(b0.y << 8) + f0.y]) * scl);
        h[1] = __floats2half2_rn(__half2float(lut_s[(b0.z << 8) + f0.z]) * scl,
                                 __half2float(lut_s[(b0.w << 8) + f0.w]) * scl);
        h[2] = __floats2half2_rn(__half2float(lut_s[(b1.x << 8) + f1.x]) * scl,
                                 __half2float(lut_s[(b1.y << 8) + f1.y]) * scl);
        h[3] = __floats2half2_rn(__half2float(lut_s[(b1.z << 8) + f1.z]) * scl,
                                 __half2float(lut_s[(b1.w << 8) + f1.w]) * scl);
        *(uint4*)&g_W[g * 8] = *(uint4*)h;
    }
}

// ---------------------------------------------------------------- pass 2 (R6+)
#define BM 128
#define BN 128
#define BKH 64                      // halves per stage (128 B per row)
#define NS (K_TOTAL / BKH)          // 64 stages
#define NSLOT 3
#define A_BYTES (BM * 128)          // 16384
#define STAGE_BYTES (2 * A_BYTES)   // A + B = 32768
#define SMEM_GEMM (NSLOT * STAGE_BYTES)  // 98304
#define THREADS 128                 // 4 warps, each 64x64

__global__ __launch_bounds__(THREADS, 2)
void ghost_gemm(float* __restrict__ out) {
    extern __shared__ char smem[];
    const uint32_t sb = smem_u32(smem);
    const int tid = threadIdx.x;
    const int warp = tid >> 5, lane = tid & 31;
    const int m0 = blockIdx.x * BM;   // M fastest -> W L2 reuse
    const int n0 = blockIdx.y * BN;

    const __half* Ag = g_xh + (size_t)m0 * K_TOTAL;
    const __half* Bg = g_W + (size_t)n0 * K_TOTAL;

    auto load_stage = [&](int s, int slot) {
        const int kh = s * BKH;
        #pragma unroll
        for (int i = 0; i < 16; i++) {
            int c = tid + i * THREADS;           // 0..2047
            int cc = c & 1023;
            int row = cc >> 3, ci = cc & 7;
            uint32_t dst = sb + slot * STAGE_BYTES + ((c < 1024) ? 0 : A_BYTES) +
                           SWZ128(row * 128 + ci * 16);
            const __half* src = (c < 1024)
                ? Ag + (size_t)row * K_TOTAL + kh + ci * 8
                : Bg + (size_t)row * K_TOTAL + kh + ci * 8;
            CP16(dst, src);
        }
        CP_COMMIT();
    };

    // warp tiling: 2 warps along M x 2 along N, each 64x64
    const int warp_m = warp & 1;
    const int warp_n = warp >> 1;

    const int a_row0 = warp_m * 64 + ((lane >> 3) & 1) * 8 + (lane & 7);
    const int a_koff = (lane >> 4) * 8;
    const int b_row0 = warp_n * 64 + ((lane >> 4) & 1) * 8 + (lane & 7);
    const int b_koff = ((lane >> 3) & 1) * 8;

    float acc[4][8][4];
    #pragma unroll
    for (int mt = 0; mt < 4; mt++)
        #pragma unroll
        for (int nt = 0; nt < 8; nt++)
            #pragma unroll
            for (int r = 0; r < 4; r++) acc[mt][nt][r] = 0.0f;

    load_stage(0, 0);
    load_stage(1, 1);

    int slot = 0;
    for (int s = 0; s < NS; ++s) {
        CP_WAIT1();
        __syncthreads();   // stage s resident; MMA(s-1) done in all warps

        // issue stage s+2 FIRST: slot (s+2)%3's last readers were MMA(s-1),
        // complete at the barrier above. Loads now fly during MMA(s) AND
        // MMA(s+1) (~2 stages of cover) instead of ~1.
        if (s + 2 < NS)
            load_stage(s + 2, (slot + 2) % NSLOT);
        else
            CP_COMMIT();   // empty group keeps wait_group accounting exact

        const uint32_t Abase = sb + slot * STAGE_BYTES;
        const uint32_t Bbase = Abase + A_BYTES;

        #pragma unroll
        for (int ks = 0; ks < 4; ks++) {
            const int k0 = ks * 16;  // halves
            uint32_t af[4][4], bf[4][4];
            #pragma unroll
            for (int mt = 0; mt < 4; mt++) {
                uint32_t ad = Abase +
                    SWZ128((a_row0 + mt * 16) * 128 + (k0 + a_koff) * 2);
                LDSM_X4(af[mt][0], af[mt][1], af[mt][2], af[mt][3], ad);
            }
            #pragma unroll
            for (int np = 0; np < 4; np++) {
                uint32_t bd = Bbase +
                    SWZ128((b_row0 + np * 16) * 128 + (k0 + b_koff) * 2);
                LDSM_X4(bf[np][0], bf[np][1], bf[np][2], bf[np][3], bd);
            }
            #pragma unroll
            for (int mt = 0; mt < 4; mt++)
                #pragma unroll
                for (int nt = 0; nt < 8; nt++)
                    MMA_F16(acc[mt][nt],
                            af[mt][0], af[mt][1], af[mt][2], af[mt][3],
                            bf[nt >> 1][(nt & 1) * 2],
                            bf[nt >> 1][(nt & 1) * 2 + 1]);
        }

        slot = (slot + 1) % NSLOT;
    }

    // epilogue
    const int qid = lane >> 2, tg = lane & 3;
    #pragma unroll
    for (int mt = 0; mt < 4; mt++) {
        #pragma unroll
        for (int nt = 0; nt < 8; nt++) {
            int row = m0 + warp_m * 64 + mt * 16 + qid;
            int col = n0 + warp_n * 64 + nt * 8 + tg * 2;
            *(float2*)&out[(size_t)row * N_TOTAL + col] =
                make_float2(acc[mt][nt][0], acc[mt][nt][1]);
            *(float2*)&out[(size_t)(row + 8) * N_TOTAL + col] =
                make_float2(acc[mt][nt][2], acc[mt][nt][3]);
        }
    }
}

extern "C" void kernel_launch(void* const* d_in, const int* in_sizes, int n_in,
                              void* d_out, int out_size) {
    const float* x        = (const float*)d_in[0];
    const int*   base_idx = (const int*)d_in[1];
    const int*   fine_idx = (const int*)d_in[2];
    const float* scale    = (const float*)d_in[3];
    const float* lut      = (const float*)d_in[4];
    float* out = (float*)d_out;

    cudaFuncSetAttribute(ghost_dequant, cudaFuncAttributeMaxDynamicSharedMemorySize,
                         131072);
    cudaFuncSetAttribute(ghost_gemm, cudaFuncAttributeMaxDynamicSharedMemorySize,
                         SMEM_GEMM);

    ghost_dequant<<<148, 1024, 131072>>>(base_idx, fine_idx, scale, lut, x);
    dim3 grid(M_TOTAL / BM, N_TOTAL / BN);  // (4, 64), M fastest
    ghost_gemm<<<grid, THREADS, SMEM_GEMM>>>(out);
}